// round 8
// baseline (speedup 1.0000x reference)
#include <cuda_runtime.h>

typedef unsigned long long u64;
typedef unsigned int u32;

#define NTH 128
#define NWARP 4
#define TILE_W 128
#define TILE_H 128
#define IMG 1024
#define STEPS (TILE_H + 10)      // 138 rows staged per CTA
#define NTRIP (STEPS / 3)        // 46 beats of 3 rows
#define NPIX (32.0f * 1024.0f * 1024.0f)

// smem geometry (u64 units): [warp][tripbuf][row012][plane][col]
#define PLANE 56                 // 448 B; 448 mod 128 == 64 -> paired planes bank-disjoint
#define ROWB  112                // 2 planes
#define TRIPB 336                // 3 rows
#define WARPR 672                // 2 triple buffers

// Normalized 11-tap Gaussian, sigma=1.5
#define W0 0.00102838f
#define W1 0.00759878f
#define W2 0.03600077f
#define W3 0.10936072f
#define W4 0.21300560f
#define W5 0.26601180f

__device__ float g_part[2048];   // one slot per CTA (write-only -> no init kernel)

__device__ __forceinline__ u64 pack2(float lo, float hi) {
    u64 r;
    asm("mov.b64 %0, {%1,%2};" : "=l"(r) : "f"(lo), "f"(hi));
    return r;
}
__device__ __forceinline__ void unpack2(u64 v, float& lo, float& hi) {
    asm("mov.b64 {%0,%1}, %2;" : "=f"(lo), "=f"(hi) : "l"(v));
}
__device__ __forceinline__ u64 ffma2(u64 a, u64 b, u64 c) {
    u64 d;
    asm("fma.rn.f32x2 %0, %1, %2, %3;" : "=l"(d) : "l"(a), "l"(b), "l"(c));
    return d;
}
__device__ __forceinline__ u64 fmul2(u64 a, u64 b) {
    u64 d;
    asm("mul.rn.f32x2 %0, %1, %2;" : "=l"(d) : "l"(a), "l"(b));
    return d;
}
__device__ __forceinline__ void lds2(u32 addr, u64& a, u64& b) {
    asm volatile("ld.shared.v2.u64 {%0,%1}, [%2];" : "=l"(a), "=l"(b) : "r"(addr));
}

// horizontal 11-tap conv on packed (x,y) pairs for 2 adjacent columns,
// rolling 4-register tap window (taps t[k] for h0, t[k+1] for h1)
__device__ __forceinline__ void hconv(u32 base, const u64* wr, u64& h0, u64& h1) {
    u64 a0, a1, b0, b1;
    lds2(base, a0, a1);            // t0 t1
    lds2(base + 16u, b0, b1);      // t2 t3
    h0 = fmul2(a0, wr[0]);  h1 = fmul2(a1, wr[0]);
    h0 = ffma2(a1, wr[1], h0);  h1 = ffma2(b0, wr[1], h1);
    h0 = ffma2(b0, wr[2], h0);  h1 = ffma2(b1, wr[2], h1);
    lds2(base + 32u, a0, a1);      // t4 t5
    h0 = ffma2(b1, wr[3], h0);  h1 = ffma2(a0, wr[3], h1);
    h0 = ffma2(a0, wr[4], h0);  h1 = ffma2(a1, wr[4], h1);
    lds2(base + 48u, b0, b1);      // t6 t7
    h0 = ffma2(a1, wr[5], h0);  h1 = ffma2(b0, wr[5], h1);
    h0 = ffma2(b0, wr[4], h0);  h1 = ffma2(b1, wr[4], h1);
    lds2(base + 64u, a0, a1);      // t8 t9
    h0 = ffma2(b1, wr[3], h0);  h1 = ffma2(a0, wr[3], h1);
    h0 = ffma2(a0, wr[2], h0);  h1 = ffma2(a1, wr[2], h1);
    lds2(base + 80u, b0, b1);      // t10 t11
    h0 = ffma2(a1, wr[1], h0);  h1 = ffma2(b0, wr[1], h1);
    h0 = ffma2(b0, wr[0], h0);  h1 = ffma2(b1, wr[0], h1);
}

__global__ __launch_bounds__(NTH, 5)
void k_ssim(const float* __restrict__ img1, const float* __restrict__ img2) {
    __shared__ __align__(16) u64 raw[NWARP * WARPR];   // 21504 B
    __shared__ float wpart[NWARP];

    u32 sbase;
    asm("{ .reg .u64 t; cvta.to.shared.u64 t, %1; cvt.u32.u64 %0, t; }"
        : "=r"(sbase) : "l"(raw));

    const int tid  = threadIdx.x;
    const int wid  = tid >> 5;
    const int lane = tid & 31;
    const int half = lane & 1;       // 0: (s,d) plane, 1: (s^2,d^2) plane
    const int pr   = lane >> 1;      // col pair within strip

    const int x0 = blockIdx.x * TILE_W + wid * 32;
    const int y0 = blockIdx.y * TILE_H;
    const int z  = blockIdx.z;
    const size_t ofs = (size_t)z * (size_t)(IMG * IMG);
    const float* p1 = img1 + ofs;
    const float* p2 = img2 + ofs;

    const u64 wr[6] = { pack2(W0, W0), pack2(W1, W1), pack2(W2, W2),
                        pack2(W3, W3), pack2(W4, W4), pack2(W5, W5) };
    const int wi[11] = { 0, 1, 2, 3, 4, 5, 4, 3, 2, 1, 0 };

    // staging columns: 42 px (image x = x0 - 5 + idx)
    const int cA = lane;
    const int cB = 32 + lane;
    const bool actB = (lane < 10);
    const int gxA = x0 - 5 + cA;
    const int gxB = x0 - 5 + cB;
    const bool okxA = ((unsigned)gxA < (unsigned)IMG);
    const bool okxB = actB && ((unsigned)gxB < (unsigned)IMG);

    u64* wr0 = raw + wid * WARPR;
    const u32 wbase = sbase + (u32)(wid * WARPR * 8);
    const u32 tapofs = (u32)((half * PLANE + 2 * pr) * 8);

    u64 ring0[11], ring1[11];        // packed (hx,hy) per staged row, 2 cols
    float ssum = 0.0f;

    // prefetch triple 0 (rows 0,1,2)
    float aA[3], bA[3], aB[3], bB[3];
#pragma unroll
    for (int r = 0; r < 3; ++r) {
        int ry = y0 - 5 + r;
        bool ok = ((unsigned)ry < (unsigned)IMG);
        const float* r1 = p1 + (size_t)ry * IMG;
        const float* r2 = p2 + (size_t)ry * IMG;
        aA[r] = (ok && okxA) ? __ldg(r1 + gxA) : 0.0f;
        bA[r] = (ok && okxA) ? __ldg(r2 + gxA) : 0.0f;
        aB[r] = (ok && okxB) ? __ldg(r1 + gxB) : 0.0f;
        bB[r] = (ok && okxB) ? __ldg(r2 + gxB) : 0.0f;
    }

    for (int Pb = 0; Pb < NTRIP; Pb += 11) {
#pragma unroll
        for (int p = 0; p < 11; ++p) {
            const int P = Pb + p;
            if (P < NTRIP) {                // uniform
                u64* bb = wr0 + (P & 1) * TRIPB;
                // ---- stage rows 3P, 3P+1, 3P+2 ----
#pragma unroll
                for (int r = 0; r < 3; ++r) {
                    float s = aA[r] + bA[r], d = aA[r] - bA[r];
                    bb[r * ROWB + cA]         = pack2(s, d);
                    bb[r * ROWB + PLANE + cA] = pack2(s * s, d * d);
                    if (actB) {
                        float s2 = aB[r] + bB[r], d2 = aB[r] - bB[r];
                        bb[r * ROWB + cB]         = pack2(s2, d2);
                        bb[r * ROWB + PLANE + cB] = pack2(s2 * s2, d2 * d2);
                    }
                }
                __syncwarp();
                // ---- prefetch next triple (rows 3P+3 .. 3P+5) ----
#pragma unroll
                for (int r = 0; r < 3; ++r) {
                    int row = 3 * P + 3 + r;
                    int ry = y0 - 5 + row;
                    bool ok = ((unsigned)ry < (unsigned)IMG) && (row < STEPS);
                    const float* r1 = p1 + (size_t)ry * IMG;
                    const float* r2 = p2 + (size_t)ry * IMG;
                    aA[r] = (ok && okxA) ? __ldg(r1 + gxA) : 0.0f;
                    bA[r] = (ok && okxA) ? __ldg(r2 + gxA) : 0.0f;
                    aB[r] = (ok && okxB) ? __ldg(r1 + gxB) : 0.0f;
                    bB[r] = (ok && okxB) ? __ldg(r2 + gxB) : 0.0f;
                }
                // ---- horizontal convs for 3 rows (independent chains) ----
                const u32 tb = wbase + (u32)((P & 1) * TRIPB * 8) + tapofs;
#pragma unroll
                for (int r = 0; r < 3; ++r) {
                    u64 h0, h1;
                    hconv(tb + (u32)(r * ROWB * 8), wr, h0, h1);
                    const int s = (3 * p + r) % 11;   // slot of row 3P+r (compile-time)
                    ring0[s] = h0;
                    ring1[s] = h1;
                }
                // ---- vertical convs + SSIM for output rows 3P-10 .. 3P-8 ----
#pragma unroll
                for (int jo = 0; jo < 3; ++jo) {
                    const int o = 3 * P - 10 + jo;
                    if (o >= 0) {                     // uniform; o <= 127 always
                        // needs rows o..o+10; slot of row o+j = (3p+1+jo+j) % 11
                        const int sb = 3 * p + 1 + jo;
                        u64 v0 = fmul2(ring0[sb % 11], wr[0]);
                        u64 v1 = fmul2(ring1[sb % 11], wr[0]);
#pragma unroll
                        for (int j = 1; j < 11; ++j) {
                            const int s = (sb + j) % 11;
                            v0 = ffma2(ring0[s], wr[wi[j]], v0);
                            v1 = ffma2(ring1[s], wr[wi[j]], v1);
                        }
                        u64 q0 = __shfl_xor_sync(0xffffffffu, v0, 1);
                        u64 q1 = __shfl_xor_sync(0xffffffffu, v1, 1);
                        u64 ab = half ? q1 : v0;   // (A,B) = conv(s), conv(d)
                        u64 pq = half ? v1 : q0;   // (P,Q) = conv(s^2), conv(d^2)
                        float A, B, Pv, Q;
                        unpack2(ab, A, B);
                        unpack2(pq, Pv, Q);
                        float A2 = A * A, B2 = B * B;
                        float cross = 0.5f * (A2 - B2);   // 2*mu1*mu2
                        float sums  = 0.5f * (A2 + B2);   // mu1^2 + mu2^2
                        float t12   = 0.5f * (Pv - Q);    // 2*conv(i1*i2)
                        float tss   = 0.5f * (Pv + Q);    // conv(i1^2+i2^2)
                        float num = (cross + 1e-4f) * (t12 - cross + 9e-4f);
                        float den = (sums  + 1e-4f) * (tss - sums  + 9e-4f);
                        ssum += __fdividef(num, den);
                    }
                }
            }
        }
    }

    // reduction: warp -> smem -> one global write per CTA
#pragma unroll
    for (int off = 16; off > 0; off >>= 1)
        ssum += __shfl_xor_sync(0xffffffffu, ssum, off);
    if (lane == 0) wpart[wid] = ssum;
    __syncthreads();
    if (tid == 0) {
        float acc = 0.0f;
#pragma unroll
        for (int w = 0; w < NWARP; ++w) acc += wpart[w];
        g_part[(z * 8 + blockIdx.y) * 8 + blockIdx.x] = acc;
    }
}

__global__ void k_final(float* out) {
    __shared__ float wp[4];
    const int tid = threadIdx.x;    // 128 threads
    float s = 0.0f;
#pragma unroll
    for (int k = 0; k < 16; ++k)
        s += g_part[tid + 128 * k];
#pragma unroll
    for (int off = 16; off > 0; off >>= 1)
        s += __shfl_xor_sync(0xffffffffu, s, off);
    if ((tid & 31) == 0) wp[tid >> 5] = s;
    __syncthreads();
    if (tid == 0)
        out[0] = 1.0f - (wp[0] + wp[1] + wp[2] + wp[3]) * (1.0f / NPIX);
}

extern "C" void kernel_launch(void* const* d_in, const int* in_sizes, int n_in,
                              void* d_out, int out_size) {
    const float* img1 = (const float*)d_in[0];
    const float* img2 = (const float*)d_in[1];
    float* out = (float*)d_out;

    dim3 grid(IMG / TILE_W, IMG / TILE_H, 32);
    k_ssim<<<grid, NTH>>>(img1, img2);
    k_final<<<1, 128>>>(out);
}